// round 6
// baseline (speedup 1.0000x reference)
#include <cuda_runtime.h>

// context_window: out[b, f*11 + c, t] = x[b, f, t + c - 5], zero-padded in t.
// x: (32, 80, 3000) fp32 -> out: (32, 880, 3000) fp32.
//
// R6: 256-bit vector memory ops (sm_100+ LDG.E.256 / STG.E.256).
// Each thread owns 8 time positions: 3x ld.global.v8 window loads
// (x[t-8..t+15], 32B-aligned) -> 11x st.global.cs.v8 stores, each warp-store
// 1024B fully contiguous. 14 memory instructions per 11264B stored (vs 32
// equivalent in the 128-bit R1 kernel) to unload the L1tex store path.

#define T_DIM   3000
#define C_LEN   11
#define ROWS    (32 * 80)     // 2560
#define T8      (T_DIM / 8)   // 375

__device__ __forceinline__ void ldg_v8(const float* p, float* d) {
    asm volatile("ld.global.nc.v8.f32 {%0,%1,%2,%3,%4,%5,%6,%7}, [%8];"
                 : "=f"(d[0]), "=f"(d[1]), "=f"(d[2]), "=f"(d[3]),
                   "=f"(d[4]), "=f"(d[5]), "=f"(d[6]), "=f"(d[7])
                 : "l"(p));
}

__device__ __forceinline__ void stg_cs_v8(float* p, const float* s) {
    asm volatile("st.global.cs.v8.f32 [%0], {%1,%2,%3,%4,%5,%6,%7,%8};"
                 :: "l"(p),
                    "f"(s[0]), "f"(s[1]), "f"(s[2]), "f"(s[3]),
                    "f"(s[4]), "f"(s[5]), "f"(s[6]), "f"(s[7])
                 : "memory");
}

__global__ __launch_bounds__(128) void context_window_kernel(
    const float* __restrict__ x, float* __restrict__ out)
{
    int t8 = blockIdx.x * blockDim.x + threadIdx.x;
    if (t8 >= T8) return;
    int row = blockIdx.y;                 // b*80 + f
    int t = t8 * 8;

    const float* __restrict__ xr = x + row * T_DIM;

    // Register window w[k] = x[t-8+k], k = 0..23.
    // out[c, t+j] = x[t + j + c - 5] = w[j + c + 3]; j = 0..7, c = 0..10.
    float w[24];

    if (t8 >= 1 && t8 < T8 - 1) {
        // Fast path: 3 aligned 256-bit loads, fully in-range
        // (t-8 >= 0 and t+15 <= 2999).
        ldg_v8(xr + t - 8, w);
        ldg_v8(xr + t,     w + 8);
        ldg_v8(xr + t + 8, w + 16);
    } else {
        // Edge path (t8 in {0, 374}): scalar bounds-checked loads.
        #pragma unroll
        for (int k = 0; k < 24; k++) {
            int idx = t - 8 + k;
            w[k] = (idx >= 0 && idx < T_DIM) ? xr[idx] : 0.0f;
        }
    }

    // 11 contiguous 256-bit streaming stores (warp-wide 1024B each).
    float* __restrict__ orow = out + (row * C_LEN) * T_DIM + t;
    #pragma unroll
    for (int c = 0; c < C_LEN; c++) {
        stg_cs_v8(orow + c * T_DIM, w + c + 3);
    }
}

extern "C" void kernel_launch(void* const* d_in, const int* in_sizes, int n_in,
                              void* d_out, int out_size)
{
    const float* x = (const float*)d_in[0];
    float* out = (float*)d_out;

    dim3 block(128);
    dim3 grid((T8 + 127) / 128, ROWS);   // (3, 2560)
    context_window_kernel<<<grid, block>>>(x, out);
}